// round 11
// baseline (speedup 1.0000x reference)
#include <cuda_runtime.h>
#include <math.h>

#define N_NODES 12288
#define N_EDGES 196608
#define F_IN    1433
#define H1      32
#define H2      16
#define NCLS    7

#define ROWS_PB 32          // rows per block
#define KC      16          // k per chunk (halved for double-buffering)
#define NWARP   8           // warps per block, K-split 8
#define KWSPAN  180         // k span per warp (8*180 = 1440 >= 1433)
#define NCH     12          // chunks per warp (12*16 = 192 >= 180, zero-padded)
#define XSTR    36          // k-row stride (mult of 4 -> 16B-aligned consume)
#define CHF     (KC * XSTR)             // floats per warp-chunk = 576
#define BUFF    (NWARP * CHF)           // floats per buffer = 4608

// ---- scratch (static device globals; no allocation allowed) ----
__device__ float g_xw  [N_NODES * H1];
__device__ float g_h   [N_NODES * H1];
__device__ float g_agg1[N_NODES * H1];
__device__ float g_agg2[N_NODES * H1];
__device__ float g_deg [N_NODES];
__device__ float g_cnt [N_NODES];
__device__ int   g_row [N_EDGES];
__device__ int   g_col [N_EDGES];

typedef unsigned long long ull;

// packed f32x2 fma: acc = a*b + acc
#define FFMA2(acc, a, b) \
    asm("fma.rn.f32x2 %0, %1, %2, %0;" : "+l"(acc) : "l"(a), "l"(b))

__device__ __forceinline__ ull rep2(float v) {
    ull r; asm("mov.b64 %0, {%1, %1};" : "=l"(r) : "f"(v)); return r;
}
__device__ __forceinline__ float2 unpk(ull v) {
    float2 f; asm("mov.b64 {%0, %1}, %2;" : "=f"(f.x), "=f"(f.y) : "l"(v)); return f;
}
__device__ __forceinline__ void red4(float* p, float a, float b, float c, float d) {
    asm volatile("red.global.add.v4.f32 [%0], {%1, %2, %3, %4};"
                 :: "l"(p), "f"(a), "f"(b), "f"(c), "f"(d) : "memory");
}
// 4B async copy with zero-fill when sz==0
__device__ __forceinline__ void cpa4(unsigned dst, const float* src, int sz) {
    asm volatile("cp.async.ca.shared.global [%0], [%1], 4, %2;"
                 :: "r"(dst), "l"(src), "r"(sz));
}

// ---- launch 1: zero agg1, init deg/cnt ----
__global__ void k_init_a() {
    int i = blockIdx.x * blockDim.x + threadIdx.x;
    if (i < N_NODES * H1) g_agg1[i] = 0.f;
    if (i < N_NODES) { g_deg[i] = 1.f; g_cnt[i] = 0.f; }
}
// ---- launch 2: zero agg2 ----
__global__ void k_init_b() {
    int i = blockIdx.x * blockDim.x + threadIdx.x;
    if (i < N_NODES * H1) g_agg2[i] = 0.f;
}

// ---- launch 3: probe dtype + decode indices + degree/count atomics ----
__global__ void k_decode(const int* __restrict__ ei32) {
    int v = ei32[2 * threadIdx.x + 1] | ei32[2 * threadIdx.x + 513];
    int is64 = !__syncthreads_or(v != 0);

    int e = blockIdx.x * blockDim.x + threadIdx.x;
    if (e >= N_EDGES) return;
    int r, c;
    if (is64) {
        r = ei32[2 * e];
        c = ei32[2 * (N_EDGES + e)];
    } else {
        r = ei32[e];
        c = ei32[N_EDGES + e];
    }
    g_row[e] = r;
    g_col[e] = c;
    atomicAdd(&g_deg[c], 1.f);
    atomicAdd(&g_cnt[r], 1.f);
}

// ---- launch 4 (profiled slot): xw = x @ W1 ----
// 256 thr / 8 warps split K (180 each); warp tile 32r x 32c, thread tile 8r x 4c.
// x staged transposed into double-buffered smem via cp.async (no prefetch regs).
#define GBODY(WV) { \
    const float* xk = sxw + kk * XSTR + rg * 8; \
    ulonglong2 xa = *(const ulonglong2*)(xk); \
    ulonglong2 xb = *(const ulonglong2*)(xk + 4); \
    ull w0 = rep2((WV).x), w1 = rep2((WV).y), w2 = rep2((WV).z), w3 = rep2((WV).w); \
    FFMA2(acc[0][0], xa.x, w0); FFMA2(acc[0][1], xa.x, w1); \
    FFMA2(acc[0][2], xa.x, w2); FFMA2(acc[0][3], xa.x, w3); \
    FFMA2(acc[1][0], xa.y, w0); FFMA2(acc[1][1], xa.y, w1); \
    FFMA2(acc[1][2], xa.y, w2); FFMA2(acc[1][3], xa.y, w3); \
    FFMA2(acc[2][0], xb.x, w0); FFMA2(acc[2][1], xb.x, w1); \
    FFMA2(acc[2][2], xb.x, w2); FFMA2(acc[2][3], xb.x, w3); \
    FFMA2(acc[3][0], xb.y, w0); FFMA2(acc[3][1], xb.y, w1); \
    FFMA2(acc[3][2], xb.y, w2); FFMA2(acc[3][3], xb.y, w3); }

__global__ void __launch_bounds__(256, 3) k_gemm1(const float* __restrict__ x,
                                                  const float* __restrict__ W1) {
    __shared__ __align__(16) float sxt[2 * BUFF];   // 9216 floats = 36.9 KB

    const int tid  = threadIdx.x;
    const int wid  = tid >> 5;
    const int lane = tid & 31;
    const int rg   = lane >> 3;     // rows rg*8 .. rg*8+7
    const int cg   = lane & 7;      // cols cg*4 .. cg*4+3
    const int row0 = blockIdx.x * ROWS_PB;

    const int kbase = wid * KWSPAN;
    const int kend  = min(F_IN, kbase + KWSPAN);
    const float* xrow = x + (size_t)row0 * F_IN;

    // cp.async mapping: this thread copies k = kbase+ch*KC+(lane&15),
    // rows (lane>>4)*16 .. +15, into sxw[(lane&15)*XSTR + row]
    const int kl   = lane & 15;
    const int rh   = (lane >> 4) * 16;
    const unsigned sbase = (unsigned)__cvta_generic_to_shared(sxt) + 4u * (wid * CHF + kl * XSTR + rh);

    ull acc[4][4];
#pragma unroll
    for (int p = 0; p < 4; p++)
#pragma unroll
        for (int c = 0; c < 4; c++) acc[p][c] = 0ull;

    // prologue: stage chunk 0 into buffer 0
    {
        const int kg = kbase + kl;
        const int sz = (kg < kend) ? 4 : 0;
        const float* gp = xrow + (size_t)rh * F_IN + min(kg, F_IN - 1);
#pragma unroll
        for (int r = 0; r < 16; r++)
            cpa4(sbase + 4u * r, gp + (size_t)r * F_IN, sz);
        asm volatile("cp.async.commit_group;" ::: "memory");
    }

    for (int ch = 0; ch < NCH; ch++) {
        // stage next chunk into the other buffer (empty group past the end)
        if (ch + 1 < NCH) {
            const int kg = kbase + (ch + 1) * KC + kl;
            const int sz = (kg < kend) ? 4 : 0;
            const float* gp = xrow + (size_t)rh * F_IN + min(kg, F_IN - 1);
            const unsigned sdst = sbase + ((ch + 1) & 1) * (4u * BUFF);
#pragma unroll
            for (int r = 0; r < 16; r++)
                cpa4(sdst + 4u * r, gp + (size_t)r * F_IN, sz);
        }
        asm volatile("cp.async.commit_group;" ::: "memory");
        asm volatile("cp.async.wait_group 1;" ::: "memory");
        __syncwarp();

        const float* sxw = sxt + (ch & 1) * BUFF + wid * CHF;
        const int k0 = kbase + ch * KC;
        if (k0 + KC <= F_IN) {   // fast path: W chunk fully in range
            const float4* wp = (const float4*)(W1) + (size_t)k0 * (H1 / 4) + cg;
#pragma unroll
            for (int kk = 0; kk < KC; kk++) {
                float4 wv = __ldg(wp + kk * (H1 / 4));
                GBODY(wv);
            }
        } else {                 // rare tail: clamp W row (x is zero-filled there)
#pragma unroll
            for (int kk = 0; kk < KC; kk++) {
                int kr = min(k0 + kk, F_IN - 1);
                float4 wv = __ldg((const float4*)(W1) + (size_t)kr * (H1 / 4) + cg);
                GBODY(wv);
            }
        }
        __syncwarp();   // all reads of this buffer done before it is re-staged
    }

    // cross-warp reduction over 8 partials; sred aliases sxt (8192 <= 9216 floats)
    __syncthreads();
    float* sred = sxt;
#pragma unroll
    for (int p = 0; p < 4; p++) {
        float2 v0 = unpk(acc[p][0]), v1 = unpk(acc[p][1]);
        float2 v2 = unpk(acc[p][2]), v3 = unpk(acc[p][3]);
        int re = rg * 8 + 2 * p;
        *(float4*)(sred + wid * (ROWS_PB * H1) + re * H1 + cg * 4) =
            make_float4(v0.x, v1.x, v2.x, v3.x);
        *(float4*)(sred + wid * (ROWS_PB * H1) + (re + 1) * H1 + cg * 4) =
            make_float4(v0.y, v1.y, v2.y, v3.y);
    }
    __syncthreads();

    // 256 float4 outputs, one per thread; sum 8 partials
    const float4* sp = (const float4*)sred;
    float4 a = sp[tid];
#pragma unroll
    for (int w = 1; w < NWARP; w++) {
        float4 b = sp[tid + w * 256];
        a.x += b.x; a.y += b.y; a.z += b.z; a.w += b.w;
    }
    ((float4*)(g_xw + (size_t)row0 * H1))[tid] = a;
}

// ---- launch 5: GCN scatter: agg1[r] += dis[r]*dis[c]*xw[c], 8 lanes/edge, red.v4 ----
__global__ void k_scatter1() {
    int t = blockIdx.x * blockDim.x + threadIdx.x;
    int e = t >> 3;
    if (e >= N_EDGES) return;
    int g = t & 7;
    int r = g_row[e];
    int c = g_col[e];
    float w = rsqrtf(g_deg[r]) * rsqrtf(g_deg[c]);
    float4 v = *(const float4*)(g_xw + c * H1 + g * 4);
    red4(g_agg1 + r * H1 + g * 4, w * v.x, w * v.y, w * v.z, w * v.w);
}

// ---- launch 6: h = relu(agg1 + selfloop + b1) ----
__global__ void k_hidden(const float* __restrict__ b1) {
    int i = blockIdx.x * blockDim.x + threadIdx.x;
    if (i >= N_NODES * H1) return;
    int node = i >> 5;
    int c    = i & 31;
    float d = rsqrtf(g_deg[node]);
    float v = g_agg1[i] + d * d * g_xw[i] + __ldg(b1 + c);
    g_h[i] = fmaxf(v, 0.f);
}

// ---- launch 7: SAGE scatter: agg2[src] += h[dst], 8 lanes/edge, red.v4 ----
__global__ void k_scatter2() {
    int t = blockIdx.x * blockDim.x + threadIdx.x;
    int e = t >> 3;
    if (e >= N_EDGES) return;
    int g = t & 7;
    int r = g_row[e];
    int c = g_col[e];
    float4 v = *(const float4*)(g_h + c * H1 + g * 4);
    red4(g_agg2 + r * H1 + g * 4, v.x, v.y, v.z, v.w);
}

// ---- launch 8: head ----
__global__ void __launch_bounds__(256) k_head(const float* __restrict__ Wl,
                                              const float* __restrict__ bl,
                                              const float* __restrict__ Wr,
                                              const float* __restrict__ br,
                                              const float* __restrict__ W3,
                                              const float* __restrict__ b3,
                                              float* __restrict__ out) {
    const unsigned FULL = 0xffffffffu;
    int gw   = (blockIdx.x * blockDim.x + threadIdx.x) >> 5;
    int lane = threadIdx.x & 31;
    if (gw >= N_NODES) return;

    float hv = g_h[gw * H1 + lane];
    float av = g_agg2[gw * H1 + lane];
    float cv = g_cnt[gw];
    av = (cv > 0.f) ? av / cv : 0.f;

    float o = 0.f;
    if (lane < H2) o = __ldg(bl + lane) + __ldg(br + lane);
#pragma unroll
    for (int k = 0; k < H1; k++) {
        float hk = __shfl_sync(FULL, hv, k);
        float ak = __shfl_sync(FULL, av, k);
        if (lane < H2)
            o = fmaf(hk, __ldg(Wl + k * H2 + lane),
                fmaf(ak, __ldg(Wr + k * H2 + lane), o));
    }
    o = fmaxf(o, 0.f);

    float ss = o * o;
#pragma unroll
    for (int off = 8; off > 0; off >>= 1) ss += __shfl_xor_sync(FULL, ss, off);
    float inv = 1.f / (sqrtf(ss) + 1e-6f);
    float on  = o * inv;

    float l = (lane < NCLS) ? __ldg(b3 + lane) : -1e30f;
#pragma unroll
    for (int c = 0; c < H2; c++) {
        float oc = __shfl_sync(FULL, on, c);
        if (lane < NCLS) l = fmaf(oc, __ldg(W3 + c * NCLS + lane), l);
    }

    float m = l;
#pragma unroll
    for (int off = 4; off > 0; off >>= 1) m = fmaxf(m, __shfl_xor_sync(FULL, m, off));
    float ev = expf(l - m);
    float sm = ev;
#pragma unroll
    for (int off = 4; off > 0; off >>= 1) sm += __shfl_xor_sync(FULL, sm, off);

    if (lane < NCLS) out[gw * NCLS + lane] = ev / sm;
}

extern "C" void kernel_launch(void* const* d_in, const int* in_sizes, int n_in,
                              void* d_out, int out_size) {
    const float* x  = (const float*)d_in[0];
    const int*   ei = (const int*)d_in[1];
    const float* W1 = (const float*)d_in[2];
    const float* b1 = (const float*)d_in[3];
    const float* Wl = (const float*)d_in[4];
    const float* bl = (const float*)d_in[5];
    const float* Wr = (const float*)d_in[6];
    const float* br = (const float*)d_in[7];
    const float* W3 = (const float*)d_in[8];
    const float* b3 = (const float*)d_in[9];
    float* out = (float*)d_out;

    const int T = 256;
    k_init_a<<<(N_NODES * H1 + T - 1) / T, T>>>();                 // 1
    k_init_b<<<(N_NODES * H1 + T - 1) / T, T>>>();                 // 2
    k_decode<<<(N_EDGES + T - 1) / T, T>>>(ei);                    // 3
    k_gemm1<<<N_NODES / ROWS_PB, 256>>>(x, W1);                    // 4 (profiled)
    k_scatter1<<<(N_EDGES * 8 + T - 1) / T, T>>>();                // 5
    k_hidden<<<(N_NODES * H1 + T - 1) / T, T>>>(b1);               // 6
    k_scatter2<<<(N_EDGES * 8 + T - 1) / T, T>>>();                // 7
    k_head<<<(N_NODES + 7) / 8, T>>>(Wl, bl, Wr, br, W3, b3, out); // 8
}